// round 5
// baseline (speedup 1.0000x reference)
#include <cuda_runtime.h>

// R5: single fused kernel. Block = 8 batches, 512 threads.
// Phase 1: stash 55 weight scalars in smem.
// Phase 2: compute the 640-entry (dig,t) Q/K/V table in-block (SoA smem).
// Phase 3: per-token build -> per-batch k/v pair-interleaved smem + Q smem.
// Phase 4: attention loop. Warp = (4 batches x 8 consecutive tokens);
//          lane=(b,dt). k/v loads: 4 distinct addresses, bank-separated
//          (batch stride 132 words) -> 1 wavefront each. Uniform loop bound
//          per warp: main part unmasked, last 4 iters bias-masked (-200).
// Phase 5: epilogue per token (residual, SwiGLU, final RMS, logits->gmem).

#define TT 64
#define GB 8
#define NTH 512
#define VOCAB 10
#define KVSTR 132          // words per batch row (32 pairs * 4 + 4 pad)
#define QSTR 66            // u64 per batch row (64 + 2 pad)

typedef unsigned long long u64;

__device__ __forceinline__ float ex2f(float x) {
    float y; asm("ex2.approx.ftz.f32 %0, %1;" : "=f"(y) : "f"(x)); return y;
}
__device__ __forceinline__ float rcpf(float x) {
    float y; asm("rcp.approx.ftz.f32 %0, %1;" : "=f"(y) : "f"(x)); return y;
}
__device__ __forceinline__ u64 pack2(float lo, float hi) {
    u64 r; asm("mov.b64 %0, {%1, %2};" : "=l"(r) : "f"(lo), "f"(hi)); return r;
}
__device__ __forceinline__ void unpack2(u64 v, float& lo, float& hi) {
    asm("mov.b64 {%0, %1}, %2;" : "=f"(lo), "=f"(hi) : "l"(v));
}
__device__ __forceinline__ u64 fma2(u64 a, u64 b, u64 c) {
    u64 d; asm("fma.rn.f32x2 %0, %1, %2, %3;" : "=l"(d) : "l"(a), "l"(b), "l"(c)); return d;
}
__device__ __forceinline__ u64 mul2(u64 a, u64 b) {
    u64 d; asm("mul.rn.f32x2 %0, %1, %2;" : "=l"(d) : "l"(a), "l"(b)); return d;
}
__device__ __forceinline__ u64 add2(u64 a, u64 b) {
    u64 d; asm("add.rn.f32x2 %0, %1, %2;" : "=l"(d) : "l"(a), "l"(b)); return d;
}

// wsm layout: [0..2] w_ln2, [3..5] w_lnf, [6..17] Wq, [18..23] Wg,
//             [24..29] Wu, [30..35] Wd, [36..38] w_ln1, [39..42] w_qn, [43..54] Wk
__global__ __launch_bounds__(NTH, 3)
void adder_fused(
    const int* __restrict__ idx,
    const float* __restrict__ pA,
    const float* __restrict__ pS,
    const float* __restrict__ pD,
    const float* __restrict__ w_ln1,
    const float* __restrict__ w_ln2,
    const float* __restrict__ w_lnf,
    const float* __restrict__ w_qn,
    const float* __restrict__ Wq,
    const float* __restrict__ Wk,
    const float* __restrict__ Wg,
    const float* __restrict__ Wu,
    const float* __restrict__ Wd,
    float* __restrict__ out)
{
    __shared__ float tab[12 * VOCAB * TT];                    // SoA table
    __shared__ __align__(16) float smK01[GB * KVSTR];
    __shared__ __align__(16) float smK23[GB * KVSTR];
    __shared__ __align__(16) float smV01[GB * KVSTR];
    __shared__ __align__(16) float smV23[GB * KVSTR];
    __shared__ u64 smQxy[GB * QSTR];
    __shared__ u64 smQzw[GB * QSTR];
    __shared__ float wsm[55];
    __shared__ float2 tok2[VOCAB];
    __shared__ float pe[TT];
    __shared__ int digs[GB * TT];

    const int tid = threadIdx.x;

    // ---- phase 1: weights to smem ----
    if (tid < 55) {
        float v;
        if      (tid < 3)  v = w_ln2[tid];
        else if (tid < 6)  v = w_lnf[tid - 3];
        else if (tid < 18) v = Wq[tid - 6];
        else if (tid < 24) v = Wg[tid - 18];
        else if (tid < 30) v = Wu[tid - 24];
        else if (tid < 36) v = Wd[tid - 30];
        else if (tid < 39) v = w_ln1[tid - 36];
        else if (tid < 43) v = w_qn[tid - 39];
        else               v = Wk[tid - 43];
        wsm[tid] = v;
    }
    const float A = pA[0], ast = pS[0], astr = pD[0];
    __syncthreads();

    // ---- phase 2: 640-entry table ----
    const int N = VOCAB * TT;
    for (int e = tid; e < N; e += NTH) {
        const int dig = e >> 6, t = e & 63;
        float sa, ca;
        sincosf(ast + (float)dig * astr, &sa, &ca);
        const float x0 = A * ca;
        const float x1 = A * sa;
        const float x2 = sinf((float)t * 1.0e-4f);
        if (t == 0)   tok2[dig] = make_float2(x0, x1);
        if (dig == 0) pe[t] = x2;

        const float r = rsqrtf((x0*x0 + x1*x1 + x2*x2) * (1.0f/3.0f) + 1e-6f);
        const float h0 = x0 * r * wsm[36];
        const float h1 = x1 * r * wsm[37];
        const float h2 = x2 * r * wsm[38];

        float qr[4], kv[4];
#pragma unroll
        for (int j = 0; j < 4; ++j) {
            qr[j] = h0 * wsm[6 + j*3] + h1 * wsm[7 + j*3] + h2 * wsm[8 + j*3];
            kv[j] = h0 * wsm[43 + j*3] + h1 * wsm[44 + j*3] + h2 * wsm[45 + j*3];
        }
        const float rq = rsqrtf((qr[0]*qr[0]+qr[1]*qr[1]+qr[2]*qr[2]+qr[3]*qr[3]) * 0.25f + 1e-6f);
        const float rk = rsqrtf((kv[0]*kv[0]+kv[1]*kv[1]+kv[2]*kv[2]+kv[3]*kv[3]) * 0.25f + 1e-6f);
        const float q0 = qr[0]*rq*wsm[39], q1 = qr[1]*rq*wsm[40];
        const float q2 = qr[2]*rq*wsm[41], q3 = qr[3]*rq*wsm[42];
        const float k0 = kv[0]*rk*wsm[39], k1 = kv[1]*rk*wsm[40];
        const float k2 = kv[2]*rk*wsm[41], k3 = kv[3]*rk*wsm[42];

        float s0, c0, s1, c1;
        sincosf((float)t, &s0, &c0);
        sincosf((float)t * 0.57735026918962576f, &s1, &c1);

        const float SC = 0.5f * 1.4426950408889634f;
        tab[0*N + e] = (q0*c0 - q1*s0) * SC;
        tab[1*N + e] = (q0*s0 + q1*c0) * SC;
        tab[2*N + e] = (q2*c1 - q3*s1) * SC;
        tab[3*N + e] = (q2*s1 + q3*c1) * SC;
        tab[4*N + e] = k0*c0 - k1*s0;
        tab[5*N + e] = k0*s0 + k1*c0;
        tab[6*N + e] = k2*c1 - k3*s1;
        tab[7*N + e] = k2*s1 + k3*c1;
        tab[8*N + e] = kv[0];
        tab[9*N + e] = kv[1];
        tab[10*N + e] = kv[2];
        tab[11*N + e] = kv[3];
    }
    __syncthreads();

    // ---- phase 3: per-token build (linear mapping; conflict-free gathers) ----
    {
        const int b = tid >> 6, t = tid & 63;
        const int dig = idx[(size_t)(blockIdx.x * GB + b) * TT + t];
        digs[tid] = dig;
        const int e = dig * TT + t;
        smQxy[b*QSTR + t] = pack2(tab[0*N+e], tab[1*N+e]);
        smQzw[b*QSTR + t] = pack2(tab[2*N+e], tab[3*N+e]);
        const int wd = b*KVSTR + 4*(t >> 1) + (t & 1);
        smK01[wd] = tab[4*N+e];  smK01[wd+2] = tab[5*N+e];
        smK23[wd] = tab[6*N+e];  smK23[wd+2] = tab[7*N+e];
        smV01[wd] = tab[8*N+e];  smV01[wd+2] = tab[9*N+e];
        smV23[wd] = tab[10*N+e]; smV23[wd+2] = tab[11*N+e];
    }
    __syncthreads();

    // ---- phase 4: attention loop ----
    const int w    = tid >> 5;
    const int lane = tid & 31;
    const int h    = w & 1;            // batch half
    const int o    = w >> 1;           // token octave 0..7
    const int b    = 4*h + (lane & 3);
    const int t    = 8*o + (lane >> 2);
    const int np   = (t + 1) >> 1;

    float Qx, Qy, Qz, Qw_;
    unpack2(smQxy[b*QSTR + t], Qx, Qy);
    unpack2(smQzw[b*QSTR + t], Qz, Qw_);
    const u64 Q0d = pack2(Qx, Qx), Q1d = pack2(Qy, Qy);
    const u64 Q2d = pack2(Qz, Qz), Q3d = pack2(Qw_, Qw_);

    const ulonglong2* k01 = (const ulonglong2*)(smK01 + b*KVSTR);
    const ulonglong2* k23 = (const ulonglong2*)(smK23 + b*KVSTR);
    const ulonglong2* v01 = (const ulonglong2*)(smV01 + b*KVSTR);
    const ulonglong2* v23 = (const ulonglong2*)(smV23 + b*KVSTR);

    u64 sd = 0ULL, axd = 0ULL, ayd = 0ULL, azd = 0ULL, awd = 0ULL;
    const int npmin = 4 * o;           // min np over warp lanes

#pragma unroll 2
    for (int i = 0; i < npmin; ++i) {
        const ulonglong2 ka = k01[i], kb = k23[i];
        const u64 sc = fma2(Q0d, ka.x, fma2(Q1d, ka.y, fma2(Q2d, kb.x, mul2(Q3d, kb.y))));
        float lo, hi; unpack2(sc, lo, hi);
        const u64 p = pack2(ex2f(lo), ex2f(hi));
        const ulonglong2 va = v01[i], vb = v23[i];
        sd  = add2(sd, p);
        axd = fma2(p, va.x, axd); ayd = fma2(p, va.y, ayd);
        azd = fma2(p, vb.x, azd); awd = fma2(p, vb.y, awd);
    }
#pragma unroll
    for (int j = 0; j < 4; ++j) {
        const int i = npmin + j;
        const float mf = (i < np) ? 0.0f : -200.0f;
        const u64 mb = pack2(mf, mf);
        const ulonglong2 ka = k01[i], kb = k23[i];
        const u64 sc = fma2(Q0d, ka.x, fma2(Q1d, ka.y, fma2(Q2d, kb.x, fma2(Q3d, kb.y, mb))));
        float lo, hi; unpack2(sc, lo, hi);
        const u64 p = pack2(ex2f(lo), ex2f(hi));
        const ulonglong2 va = v01[i], vb = v23[i];
        sd  = add2(sd, p);
        axd = fma2(p, va.x, axd); ayd = fma2(p, va.y, ayd);
        azd = fma2(p, vb.x, azd); awd = fma2(p, vb.y, awd);
    }

    float lo, hi;
    unpack2(sd, lo, hi);  float sum = lo + hi;
    unpack2(axd, lo, hi); float o0 = lo + hi;
    unpack2(ayd, lo, hi); float o1 = lo + hi;
    unpack2(azd, lo, hi); float o2 = lo + hi;
    unpack2(awd, lo, hi); float o3 = lo + hi;

    if (!(t & 1)) {                    // self term s=t for even t
        const int wd = b*KVSTR + 2*t;  // 4*(t/2), lane 0 of pair
        const float K0s = smK01[wd], K1s = smK01[wd+2];
        const float K2s = smK23[wd], K3s = smK23[wd+2];
        const float sc = Qx*K0s + Qy*K1s + Qz*K2s + Qw_*K3s;
        const float p = ex2f(sc);
        sum += p;
        o0 += p * smV01[wd]; o1 += p * smV01[wd+2];
        o2 += p * smV23[wd]; o3 += p * smV23[wd+2];
    }

    const float inv = rcpf(sum);
    o0 *= inv; o1 *= inv; o2 *= inv; o3 *= inv;

    __syncthreads();   // scheduling fence: keep epilogue smem reads late

    // ---- phase 5: epilogue ----
    const int dig = digs[b*TT + t];
    const float2 tk = tok2[dig];
    float x0 = tk.x, x1 = tk.y, x2 = pe[t];

    x0 += o0*wsm[6] + o1*wsm[9]  + o2*wsm[12] + o3*wsm[15];
    x1 += o0*wsm[7] + o1*wsm[10] + o2*wsm[13] + o3*wsm[16];
    x2 += o0*wsm[8] + o1*wsm[11] + o2*wsm[14] + o3*wsm[17];

    float r = rsqrtf((x0*x0 + x1*x1 + x2*x2) * (1.0f/3.0f) + 1e-6f);
    const float h0 = x0 * r * wsm[0];
    const float h1 = x1 * r * wsm[1];
    const float h2 = x2 * r * wsm[2];

    const float g0 = h0*wsm[18] + h1*wsm[19] + h2*wsm[20];
    const float g1 = h0*wsm[21] + h1*wsm[22] + h2*wsm[23];
    const float u0 = h0*wsm[24] + h1*wsm[25] + h2*wsm[26];
    const float u1 = h0*wsm[27] + h1*wsm[28] + h2*wsm[29];

    const float LOG2E = 1.4426950408889634f;
    const float m0 = g0 * u0 * rcpf(1.0f + ex2f(-g0 * LOG2E));
    const float m1 = g1 * u1 * rcpf(1.0f + ex2f(-g1 * LOG2E));

    x0 += m0*wsm[30] + m1*wsm[31];
    x1 += m0*wsm[32] + m1*wsm[33];
    x2 += m0*wsm[34] + m1*wsm[35];

    r = rsqrtf((x0*x0 + x1*x1 + x2*x2) * (1.0f/3.0f) + 1e-6f);
    const float f0 = x0 * r * wsm[3];
    const float f1 = x1 * r * wsm[4];

    float2* dst = (float2*)(out + ((size_t)(blockIdx.x * GB + b) * TT + t) * VOCAB);
#pragma unroll
    for (int j = 0; j < 5; ++j) {
        const float2 ta = tok2[2*j], tb = tok2[2*j + 1];
        dst[j] = make_float2(f0*ta.x + f1*ta.y, f0*tb.x + f1*tb.y);
    }
}

extern "C" void kernel_launch(void* const* d_in, const int* in_sizes, int n_in,
                              void* d_out, int out_size)
{
    const int*   idx     = (const int*)  d_in[0];
    const float* arc_A   = (const float*)d_in[1];
    const float* arc_st  = (const float*)d_in[2];
    const float* arc_sd  = (const float*)d_in[3];
    const float* w_ln1   = (const float*)d_in[4];
    const float* w_ln2   = (const float*)d_in[5];
    const float* w_lnf   = (const float*)d_in[6];
    const float* w_qn    = (const float*)d_in[7];
    const float* Wq      = (const float*)d_in[8];
    const float* Wk      = (const float*)d_in[9];
    const float* Wg      = (const float*)d_in[10];
    const float* Wu      = (const float*)d_in[11];
    const float* Wd      = (const float*)d_in[12];
    float* out = (float*)d_out;

    const int B = in_sizes[0] / TT;          // 16384
    const int grid = B / GB;                 // 2048 blocks
    adder_fused<<<grid, NTH>>>(idx, arc_A, arc_st, arc_sd,
                               w_ln1, w_ln2, w_lnf, w_qn,
                               Wq, Wk, Wg, Wu, Wd, out);
}

// round 7
// speedup vs baseline: 1.8302x; 1.8302x over previous
#include <cuda_runtime.h>

// R6: R5 structure with the register strangulation removed.
// __launch_bounds__(512,2) -> 64-reg budget, no local-memory spills (R5's
// (512,3) forced 40 regs and spilled the attention loop -> 113us).
// Also drops the pre-epilogue barrier so light warps (octave 0: 8 iters)
// flow into their epilogue while heavy warps (octave 7: 36 iters) still loop.
// Block = 8 batches, 512 threads, single fused kernel:
//   P1 weights->smem, P2 640-entry (dig,t) QKV table in-block,
//   P3 per-token staging (Q packed smem + k/v pair-interleaved, batch stride
//      132 words so the 4 per-warp addresses hit distinct banks),
//   P4 attention (warp = 4 batches x 8 consecutive tokens, uniform bound,
//      last 4 iters bias-masked), P5 epilogue straight to gmem.

#define TT 64
#define GB 8
#define NTH 512
#define VOCAB 10
#define KVSTR 132          // words per batch row (32 pairs * 4 + 4 pad)
#define QSTR 66            // u64 per batch row (64 + 2 pad)

typedef unsigned long long u64;

__device__ __forceinline__ float ex2f(float x) {
    float y; asm("ex2.approx.ftz.f32 %0, %1;" : "=f"(y) : "f"(x)); return y;
}
__device__ __forceinline__ float rcpf(float x) {
    float y; asm("rcp.approx.ftz.f32 %0, %1;" : "=f"(y) : "f"(x)); return y;
}
__device__ __forceinline__ u64 pack2(float lo, float hi) {
    u64 r; asm("mov.b64 %0, {%1, %2};" : "=l"(r) : "f"(lo), "f"(hi)); return r;
}
__device__ __forceinline__ void unpack2(u64 v, float& lo, float& hi) {
    asm("mov.b64 {%0, %1}, %2;" : "=f"(lo), "=f"(hi) : "l"(v));
}
__device__ __forceinline__ u64 fma2(u64 a, u64 b, u64 c) {
    u64 d; asm("fma.rn.f32x2 %0, %1, %2, %3;" : "=l"(d) : "l"(a), "l"(b), "l"(c)); return d;
}
__device__ __forceinline__ u64 mul2(u64 a, u64 b) {
    u64 d; asm("mul.rn.f32x2 %0, %1, %2;" : "=l"(d) : "l"(a), "l"(b)); return d;
}
__device__ __forceinline__ u64 add2(u64 a, u64 b) {
    u64 d; asm("add.rn.f32x2 %0, %1, %2;" : "=l"(d) : "l"(a), "l"(b)); return d;
}

// wsm layout: [0..2] w_ln2, [3..5] w_lnf, [6..17] Wq, [18..23] Wg,
//             [24..29] Wu, [30..35] Wd, [36..38] w_ln1, [39..42] w_qn, [43..54] Wk
__global__ __launch_bounds__(NTH, 2)
void adder_fused(
    const int* __restrict__ idx,
    const float* __restrict__ pA,
    const float* __restrict__ pS,
    const float* __restrict__ pD,
    const float* __restrict__ w_ln1,
    const float* __restrict__ w_ln2,
    const float* __restrict__ w_lnf,
    const float* __restrict__ w_qn,
    const float* __restrict__ Wq,
    const float* __restrict__ Wk,
    const float* __restrict__ Wg,
    const float* __restrict__ Wu,
    const float* __restrict__ Wd,
    float* __restrict__ out)
{
    __shared__ float tab[12 * VOCAB * TT];                    // SoA table
    __shared__ __align__(16) float smK01[GB * KVSTR];
    __shared__ __align__(16) float smK23[GB * KVSTR];
    __shared__ __align__(16) float smV01[GB * KVSTR];
    __shared__ __align__(16) float smV23[GB * KVSTR];
    __shared__ u64 smQxy[GB * QSTR];
    __shared__ u64 smQzw[GB * QSTR];
    __shared__ float wsm[55];
    __shared__ float2 tok2[VOCAB];
    __shared__ float pe[TT];
    __shared__ int digs[GB * TT];

    const int tid = threadIdx.x;

    // ---- phase 1: weights to smem ----
    if (tid < 55) {
        float v;
        if      (tid < 3)  v = w_ln2[tid];
        else if (tid < 6)  v = w_lnf[tid - 3];
        else if (tid < 18) v = Wq[tid - 6];
        else if (tid < 24) v = Wg[tid - 18];
        else if (tid < 30) v = Wu[tid - 24];
        else if (tid < 36) v = Wd[tid - 30];
        else if (tid < 39) v = w_ln1[tid - 36];
        else if (tid < 43) v = w_qn[tid - 39];
        else               v = Wk[tid - 43];
        wsm[tid] = v;
    }
    const float A = pA[0], ast = pS[0], astr = pD[0];
    __syncthreads();

    // ---- phase 2: 640-entry table ----
    const int N = VOCAB * TT;
    for (int e = tid; e < N; e += NTH) {
        const int dig = e >> 6, t = e & 63;
        float sa, ca;
        sincosf(ast + (float)dig * astr, &sa, &ca);
        const float x0 = A * ca;
        const float x1 = A * sa;
        const float x2 = sinf((float)t * 1.0e-4f);
        if (t == 0)   tok2[dig] = make_float2(x0, x1);
        if (dig == 0) pe[t] = x2;

        const float r = rsqrtf((x0*x0 + x1*x1 + x2*x2) * (1.0f/3.0f) + 1e-6f);
        const float h0 = x0 * r * wsm[36];
        const float h1 = x1 * r * wsm[37];
        const float h2 = x2 * r * wsm[38];

        float qr[4], kv[4];
#pragma unroll
        for (int j = 0; j < 4; ++j) {
            qr[j] = h0 * wsm[6 + j*3] + h1 * wsm[7 + j*3] + h2 * wsm[8 + j*3];
            kv[j] = h0 * wsm[43 + j*3] + h1 * wsm[44 + j*3] + h2 * wsm[45 + j*3];
        }
        const float rq = rsqrtf((qr[0]*qr[0]+qr[1]*qr[1]+qr[2]*qr[2]+qr[3]*qr[3]) * 0.25f + 1e-6f);
        const float rk = rsqrtf((kv[0]*kv[0]+kv[1]*kv[1]+kv[2]*kv[2]+kv[3]*kv[3]) * 0.25f + 1e-6f);
        const float q0 = qr[0]*rq*wsm[39], q1 = qr[1]*rq*wsm[40];
        const float q2 = qr[2]*rq*wsm[41], q3 = qr[3]*rq*wsm[42];
        const float k0 = kv[0]*rk*wsm[39], k1 = kv[1]*rk*wsm[40];
        const float k2 = kv[2]*rk*wsm[41], k3 = kv[3]*rk*wsm[42];

        float s0, c0, s1, c1;
        sincosf((float)t, &s0, &c0);
        sincosf((float)t * 0.57735026918962576f, &s1, &c1);

        const float SC = 0.5f * 1.4426950408889634f;
        tab[0*N + e] = (q0*c0 - q1*s0) * SC;
        tab[1*N + e] = (q0*s0 + q1*c0) * SC;
        tab[2*N + e] = (q2*c1 - q3*s1) * SC;
        tab[3*N + e] = (q2*s1 + q3*c1) * SC;
        tab[4*N + e] = k0*c0 - k1*s0;
        tab[5*N + e] = k0*s0 + k1*c0;
        tab[6*N + e] = k2*c1 - k3*s1;
        tab[7*N + e] = k2*s1 + k3*c1;
        tab[8*N + e] = kv[0];
        tab[9*N + e] = kv[1];
        tab[10*N + e] = kv[2];
        tab[11*N + e] = kv[3];
    }
    __syncthreads();

    // ---- phase 3: per-token staging (conflict-free gathers) ----
    {
        const int b = tid >> 6, t = tid & 63;
        const int dig = idx[(size_t)(blockIdx.x * GB + b) * TT + t];
        digs[tid] = dig;
        const int e = dig * TT + t;
        smQxy[b*QSTR + t] = pack2(tab[0*N+e], tab[1*N+e]);
        smQzw[b*QSTR + t] = pack2(tab[2*N+e], tab[3*N+e]);
        const int wd = b*KVSTR + 4*(t >> 1) + (t & 1);
        smK01[wd] = tab[4*N+e];  smK01[wd+2] = tab[5*N+e];
        smK23[wd] = tab[6*N+e];  smK23[wd+2] = tab[7*N+e];
        smV01[wd] = tab[8*N+e];  smV01[wd+2] = tab[9*N+e];
        smV23[wd] = tab[10*N+e]; smV23[wd+2] = tab[11*N+e];
    }
    __syncthreads();

    // ---- phase 4: attention loop ----
    const int w    = tid >> 5;
    const int lane = tid & 31;
    const int h    = w & 1;            // batch half
    const int o    = w >> 1;           // token octave 0..7
    const int b    = 4*h + (lane & 3);
    const int t    = 8*o + (lane >> 2);
    const int np   = (t + 1) >> 1;

    float Qx, Qy, Qz, Qw_;
    unpack2(smQxy[b*QSTR + t], Qx, Qy);
    unpack2(smQzw[b*QSTR + t], Qz, Qw_);
    const u64 Q0d = pack2(Qx, Qx), Q1d = pack2(Qy, Qy);
    const u64 Q2d = pack2(Qz, Qz), Q3d = pack2(Qw_, Qw_);

    const ulonglong2* k01 = (const ulonglong2*)(smK01 + b*KVSTR);
    const ulonglong2* k23 = (const ulonglong2*)(smK23 + b*KVSTR);
    const ulonglong2* v01 = (const ulonglong2*)(smV01 + b*KVSTR);
    const ulonglong2* v23 = (const ulonglong2*)(smV23 + b*KVSTR);

    u64 sd = 0ULL, axd = 0ULL, ayd = 0ULL, azd = 0ULL, awd = 0ULL;
    const int npmin = 4 * o;           // min np over warp lanes

#pragma unroll 2
    for (int i = 0; i < npmin; ++i) {
        const ulonglong2 ka = k01[i], kb = k23[i];
        const u64 sc = fma2(Q0d, ka.x, fma2(Q1d, ka.y, fma2(Q2d, kb.x, mul2(Q3d, kb.y))));
        float lo, hi; unpack2(sc, lo, hi);
        const u64 p = pack2(ex2f(lo), ex2f(hi));
        const ulonglong2 va = v01[i], vb = v23[i];
        sd  = add2(sd, p);
        axd = fma2(p, va.x, axd); ayd = fma2(p, va.y, ayd);
        azd = fma2(p, vb.x, azd); awd = fma2(p, vb.y, awd);
    }
#pragma unroll
    for (int j = 0; j < 4; ++j) {
        const int i = npmin + j;
        const float mf = (i < np) ? 0.0f : -200.0f;
        const u64 mb = pack2(mf, mf);
        const ulonglong2 ka = k01[i], kb = k23[i];
        const u64 sc = fma2(Q0d, ka.x, fma2(Q1d, ka.y, fma2(Q2d, kb.x, fma2(Q3d, kb.y, mb))));
        float lo, hi; unpack2(sc, lo, hi);
        const u64 p = pack2(ex2f(lo), ex2f(hi));
        const ulonglong2 va = v01[i], vb = v23[i];
        sd  = add2(sd, p);
        axd = fma2(p, va.x, axd); ayd = fma2(p, va.y, ayd);
        azd = fma2(p, vb.x, azd); awd = fma2(p, vb.y, awd);
    }

    float lo, hi;
    unpack2(sd, lo, hi);  float sum = lo + hi;
    unpack2(axd, lo, hi); float o0 = lo + hi;
    unpack2(ayd, lo, hi); float o1 = lo + hi;
    unpack2(azd, lo, hi); float o2 = lo + hi;
    unpack2(awd, lo, hi); float o3 = lo + hi;

    if (!(t & 1)) {                    // self term s=t for even t
        const int wd = b*KVSTR + 2*t;  // 4*(t/2), element 0 of pair
        const float K0s = smK01[wd], K1s = smK01[wd+2];
        const float K2s = smK23[wd], K3s = smK23[wd+2];
        const float sc = Qx*K0s + Qy*K1s + Qz*K2s + Qw_*K3s;
        const float p = ex2f(sc);
        sum += p;
        o0 += p * smV01[wd]; o1 += p * smV01[wd+2];
        o2 += p * smV23[wd]; o3 += p * smV23[wd+2];
    }

    const float inv = rcpf(sum);
    o0 *= inv; o1 *= inv; o2 *= inv; o3 *= inv;

    // ---- phase 5: epilogue (no barrier: light warps exit early) ----
    const int dig = digs[b*TT + t];
    const float2 tk = tok2[dig];
    float x0 = tk.x, x1 = tk.y, x2 = pe[t];

    x0 += o0*wsm[6] + o1*wsm[9]  + o2*wsm[12] + o3*wsm[15];
    x1 += o0*wsm[7] + o1*wsm[10] + o2*wsm[13] + o3*wsm[16];
    x2 += o0*wsm[8] + o1*wsm[11] + o2*wsm[14] + o3*wsm[17];

    float r = rsqrtf((x0*x0 + x1*x1 + x2*x2) * (1.0f/3.0f) + 1e-6f);
    const float h0 = x0 * r * wsm[0];
    const float h1 = x1 * r * wsm[1];
    const float h2 = x2 * r * wsm[2];

    const float g0 = h0*wsm[18] + h1*wsm[19] + h2*wsm[20];
    const float g1 = h0*wsm[21] + h1*wsm[22] + h2*wsm[23];
    const float u0 = h0*wsm[24] + h1*wsm[25] + h2*wsm[26];
    const float u1 = h0*wsm[27] + h1*wsm[28] + h2*wsm[29];

    const float LOG2E = 1.4426950408889634f;
    const float m0 = g0 * u0 * rcpf(1.0f + ex2f(-g0 * LOG2E));
    const float m1 = g1 * u1 * rcpf(1.0f + ex2f(-g1 * LOG2E));

    x0 += m0*wsm[30] + m1*wsm[31];
    x1 += m0*wsm[32] + m1*wsm[33];
    x2 += m0*wsm[34] + m1*wsm[35];

    r = rsqrtf((x0*x0 + x1*x1 + x2*x2) * (1.0f/3.0f) + 1e-6f);
    const float f0 = x0 * r * wsm[3];
    const float f1 = x1 * r * wsm[4];

    float2* dst = (float2*)(out + ((size_t)(blockIdx.x * GB + b) * TT + t) * VOCAB);
#pragma unroll
    for (int j = 0; j < 5; ++j) {
        const float2 ta = tok2[2*j], tb = tok2[2*j + 1];
        dst[j] = make_float2(f0*ta.x + f1*ta.y, f0*tb.x + f1*tb.y);
    }
}

extern "C" void kernel_launch(void* const* d_in, const int* in_sizes, int n_in,
                              void* d_out, int out_size)
{
    const int*   idx     = (const int*)  d_in[0];
    const float* arc_A   = (const float*)d_in[1];
    const float* arc_st  = (const float*)d_in[2];
    const float* arc_sd  = (const float*)d_in[3];
    const float* w_ln1   = (const float*)d_in[4];
    const float* w_ln2   = (const float*)d_in[5];
    const float* w_lnf   = (const float*)d_in[6];
    const float* w_qn    = (const float*)d_in[7];
    const float* Wq      = (const float*)d_in[8];
    const float* Wk      = (const float*)d_in[9];
    const float* Wg      = (const float*)d_in[10];
    const float* Wu      = (const float*)d_in[11];
    const float* Wd      = (const float*)d_in[12];
    float* out = (float*)d_out;

    const int B = in_sizes[0] / TT;          // 16384
    const int grid = B / GB;                 // 2048 blocks
    adder_fused<<<grid, NTH>>>(idx, arc_A, arc_st, arc_sd,
                               w_ln1, w_ln2, w_lnf, w_qn,
                               Wq, Wk, Wg, Wu, Wd, out);
}